// round 16
// baseline (speedup 1.0000x reference)
#include <cuda_runtime.h>
#include <stdint.h>

#define HEADS 12
#define HD    64
#define DIM   768
#define BB    4
#define NTOK  6273          // 1 + 8*28*28
#define NQ    1569          // 1 + 8*14*14
#define NQP   1600          // padded V row pitch (16B-aligned cp.async rows)
#define GM1   25092         // BB*NTOK
#define GN1   2304          // 3*DIM
#define GM2   6276          // BB*NQ
#define ATT_SCALE 0.125f
#define AW    68            // pitch (words) all attention tiles
#define TX    30            // pool tile x extent
#define PSZ   ((size_t)BB * HEADS * NQ * HD)

// ---------------- scratch (static device globals; no allocation) ----------------
__device__ float    g_qkv[(size_t)GM1 * GN1];                    // 231 MB
__device__ unsigned g_qt [PSZ];                                  // Q tf32  [bh][tok][d]
__device__ unsigned g_kt [PSZ];                                  // K tf32  [bh][tok][d]
__device__ unsigned g_vt [(size_t)BB * HEADS * HD * NQP];        // V tf32  [bh][d][NQP]
__device__ float    g_att[(size_t)GM2 * DIM];                    // attention out (tf32 bits)
__device__ unsigned g_xt[(size_t)GM1 * DIM];                     // x -> tf32
__device__ unsigned g_wt1[(size_t)GN1 * DIM];                    // qkv_w^T tf32 [N,K]
__device__ unsigned g_wt2[(size_t)DIM * DIM];                    // proj_w^T tf32 [N,K]

// ---------------- TF32 helpers ----------------
__device__ __forceinline__ unsigned f2tf(float x) {
    unsigned u;
    asm("cvt.rna.tf32.f32 %0, %1;" : "=r"(u) : "f"(x));
    return u;
}
__device__ __forceinline__ void mma_tf32(float* c, const unsigned* a, const unsigned* b) {
    asm volatile(
        "mma.sync.aligned.m16n8k8.row.col.f32.tf32.tf32.f32 "
        "{%0,%1,%2,%3}, {%4,%5,%6,%7}, {%8,%9}, {%0,%1,%2,%3};"
        : "+f"(c[0]), "+f"(c[1]), "+f"(c[2]), "+f"(c[3])
        : "r"(a[0]), "r"(a[1]), "r"(a[2]), "r"(a[3]), "r"(b[0]), "r"(b[1]));
}
__device__ __forceinline__ void cpasync16(unsigned smaddr, const void* g, bool pred) {
    int sz = pred ? 16 : 0;
    asm volatile("cp.async.cg.shared.global [%0], [%1], 16, %2;"
                 :: "r"(smaddr), "l"(g), "r"(sz));
}
__device__ __forceinline__ void ldmx4(unsigned& r0, unsigned& r1, unsigned& r2, unsigned& r3,
                                      unsigned smaddr) {
    asm volatile("ldmatrix.sync.aligned.m8n8.x4.shared.b16 {%0,%1,%2,%3}, [%4];"
                 : "=r"(r0), "=r"(r1), "=r"(r2), "=r"(r3) : "r"(smaddr));
}

// ---------------- elementwise x -> tf32 ----------------
__global__ void cvt_tf32(const float4* __restrict__ in, uint4* __restrict__ out, int n4) {
    int i = blockIdx.x * blockDim.x + threadIdx.x;
    if (i < n4) {
        float4 v = in[i];
        out[i] = make_uint4(f2tf(v.x), f2tf(v.y), f2tf(v.z), f2tf(v.w));
    }
}

// ---------------- weight transpose + tf32 round: in[K,N] -> out[N,K] ----------------
__global__ void transpose_tf32(const float* __restrict__ in, unsigned* __restrict__ out,
                               int K, int N)
{
    __shared__ unsigned t[32][33];
    int n0 = blockIdx.x << 5, k0 = blockIdx.y << 5;
    int tx = threadIdx.x, ty = threadIdx.y;   // (32, 8)
#pragma unroll
    for (int j = ty; j < 32; j += 8)
        t[j][tx] = f2tf(in[(size_t)(k0 + j) * N + n0 + tx]);
    __syncthreads();
#pragma unroll
    for (int j = ty; j < 32; j += 8)
        out[(size_t)(n0 + j) * K + k0 + tx] = t[tx][j];
}

// ---------------- GEMM v5 (R15, at legacy-path HW cap): ldmatrix + 3-stage cp.async ---------
#define GSTG2 (2 * 128 * 36)   // words per stage = 9216
__global__ void __launch_bounds__(256, 2) gemm_tf32_ldm(
    const unsigned* __restrict__ A, const unsigned* __restrict__ Bt,
    const float* __restrict__ bias, float* __restrict__ C,
    int M, int N, int K)
{
    extern __shared__ unsigned sm[];
    const unsigned sbase = (unsigned)__cvta_generic_to_shared(sm);

    const int tid  = threadIdx.x;
    const int bn   = blockIdx.x << 7;
    const int bm   = blockIdx.y << 7;
    const int lane = tid & 31, warp = tid >> 5;
    const int wr   = warp >> 2, wc = warp & 3;
    const int gid  = lane >> 2, tg = lane & 3;

    const int aoff = ((lane & 7) + (((lane >> 3) & 1) << 3)) * 36 + ((lane >> 4) << 2);
    const int boff = ((lane & 7) + ((lane >> 4) << 3)) * 36 + (((lane >> 3) & 1) << 2);

    const int ar  = tid >> 3;
    const int ac4 = (tid & 7) << 2;

    float acc[4][4][4];
#pragma unroll
    for (int i = 0; i < 4; i++)
#pragma unroll
        for (int jn = 0; jn < 4; jn++)
#pragma unroll
            for (int r = 0; r < 4; r++) acc[i][jn][r] = 0.f;

    auto loadStage = [&](int i, int s) {
        const int k0 = i << 5;
        const unsigned so = sbase + s * (GSTG2 * 4);
#pragma unroll
        for (int it = 0; it < 4; it++) {
            int r  = ar + it * 32;
            int gr = bm + r;
            cpasync16(so + (r * 36 + ac4) * 4, A + (size_t)gr * K + k0 + ac4, gr < M);
            cpasync16(so + ((128 + r) * 36 + ac4) * 4,
                      Bt + (size_t)(bn + r) * K + k0 + ac4, true);
        }
        asm volatile("cp.async.commit_group;");
    };

    const int nIter = K >> 5;   // 24
    loadStage(0, 0);
    loadStage(1, 1);

    int sIdx = 0;
    for (int i = 0; i < nIter; i++) {
        if (i + 1 < nIter) {
            asm volatile("cp.async.wait_group 1;");
        } else {
            asm volatile("cp.async.wait_group 0;");
        }
        __syncthreads();
        if (i + 2 < nIter) {
            int s2 = sIdx + 2; if (s2 >= 3) s2 -= 3;
            loadStage(i + 2, s2);
        }

        const unsigned Abase = sbase + sIdx * (GSTG2 * 4);
        const unsigned Bbase = Abase + 128 * 36 * 4;
#pragma unroll
        for (int k8 = 0; k8 < 4; k8++) {
            const int kc = k8 << 3;
            unsigned a[4][4], bf[4][2];
#pragma unroll
            for (int ii = 0; ii < 4; ii++) {
                unsigned ad = Abase + (((wr << 6) + (ii << 4)) * 36 + kc + aoff) * 4;
                ldmx4(a[ii][0], a[ii][1], a[ii][2], a[ii][3], ad);
            }
#pragma unroll
            for (int p = 0; p < 2; p++) {
                unsigned bd = Bbase + (((wc << 5) + (p << 4)) * 36 + kc + boff) * 4;
                ldmx4(bf[2 * p][0], bf[2 * p][1], bf[2 * p + 1][0], bf[2 * p + 1][1], bd);
            }
#pragma unroll
            for (int ii = 0; ii < 4; ii++)
#pragma unroll
                for (int jn = 0; jn < 4; jn++)
                    mma_tf32(acc[ii][jn], a[ii], bf[jn]);
        }
        if (++sIdx == 3) sIdx = 0;
    }

#pragma unroll
    for (int i = 0; i < 4; i++) {
        int gr0 = bm + (wr << 6) + (i << 4) + gid;
#pragma unroll
        for (int jn = 0; jn < 4; jn++) {
            int gc = bn + (wc << 5) + (jn << 3) + (tg << 1);
            float b0 = bias[gc], b1 = bias[gc + 1];
            if (gr0 < M) {
                C[(size_t)gr0 * N + gc]     = acc[i][jn][0] + b0;
                C[(size_t)gr0 * N + gc + 1] = acc[i][jn][1] + b1;
            }
            if (gr0 + 8 < M) {
                C[(size_t)(gr0 + 8) * N + gc]     = acc[i][jn][2] + b0;
                C[(size_t)(gr0 + 8) * N + gc + 1] = acc[i][jn][3] + b1;
            }
        }
    }
}

// ---------------- pool + LN v6 (R15, unchanged) ----------------
__global__ void __launch_bounds__(896) pool_ln6(
    const float* __restrict__ qkv,
    const float* __restrict__ wq, const float* __restrict__ wk, const float* __restrict__ wv,
    const float* __restrict__ gq, const float* __restrict__ bq,
    const float* __restrict__ gk, const float* __restrict__ bk,
    const float* __restrict__ gv, const float* __restrict__ bv,
    unsigned* __restrict__ dstQ, unsigned* __restrict__ dstK, unsigned* __restrict__ dstV)
{
    extern __shared__ float sp[];
    float*    tile = sp;
    float*    wsh  = tile + 9 * TX * 64;
    float*    gsh  = wsh + 1728;
    float*    bsh  = gsh + 64;
    float*    red  = bsh + 64;
    unsigned* vst  = (unsigned*)(red + 56);

    const int slab = blockIdx.z;
    const float* wconv = slab == 0 ? wq : slab == 1 ? wk : wv;
    const float* gamma = slab == 0 ? gq : slab == 1 ? gk : gv;
    const float* beta  = slab == 0 ? bq : slab == 1 ? bk : bv;

    const int bh = blockIdx.y;
    const int b  = bh / HEADS, h = bh - b * HEADS;
    const int d  = threadIdx.x;
    const int xp = threadIdx.y;
    const int tid = d + (xp << 6);
    const bool is_cls = (blockIdx.x == 112);

    for (int i = tid; i < 1728; i += 896) wsh[i] = wconv[i];
    if (tid < 64) { gsh[tid] = gamma[tid]; bsh[tid] = beta[tid]; }

    const float* base = qkv + (size_t)b * NTOK * GN1 + slab * DIM + h * HD;

    int tp = 0, yp = 0;
    if (!is_cls) {
        tp = blockIdx.x / 14;
        yp = blockIdx.x - tp * 14;
        for (int i = tid; i < 9 * 2 * 64; i += 896) {
            int rr = i >> 7;
            int cc = (i >> 6) & 1;
            int dd = i & 63;
            tile[(rr * TX + cc * 29) * 64 + dd] = 0.f;
        }
        for (int i = tid; i < 252 * 16; i += 896) {
            int s  = i >> 4, f4 = i & 15;
            int kt = s / 84;  int r = s - kt * 84;
            int ky = r / 28;  int x = r - ky * 28;
            int t  = tp + kt - 1;
            int y  = 2 * yp + ky - 1;
            float4 v = make_float4(0.f, 0.f, 0.f, 0.f);
            if ((unsigned)t < 8u && (unsigned)y < 28u) {
                int n = 1 + (t * 28 + y) * 28 + x;
                v = *(const float4*)(base + (size_t)n * GN1 + (f4 << 2));
            }
            float* tdst = tile + ((kt * 3 + ky) * TX + x + 1) * 64 + (f4 << 2);
            tdst[0] = v.x; tdst[1] = v.y; tdst[2] = v.z; tdst[3] = v.w;
        }
    }
    __syncthreads();

    if (is_cls) {
        if (tid < 32) {
            float v0 = base[tid];
            float v1 = base[tid + 32];
            float sum = v0 + v1, sq = v0 * v0 + v1 * v1;
#pragma unroll
            for (int off = 16; off > 0; off >>= 1) {
                sum += __shfl_xor_sync(0xffffffffu, sum, off);
                sq  += __shfl_xor_sync(0xffffffffu, sq, off);
            }
            float mean = sum * (1.f / 64.f);
            float var  = sq * (1.f / 64.f) - mean * mean;
            float rstd = rsqrtf(var + 1e-5f);
            float o0 = (v0 - mean) * rstd * gsh[tid]      + bsh[tid];
            float o1 = (v1 - mean) * rstd * gsh[tid + 32] + bsh[tid + 32];
            if (slab == 0) {
                dstQ[(size_t)bh * NQ * HD + tid]      = f2tf(o0);
                dstQ[(size_t)bh * NQ * HD + tid + 32] = f2tf(o1);
            } else if (slab == 1) {
                dstK[(size_t)bh * NQ * HD + tid]      = f2tf(o0);
                dstK[(size_t)bh * NQ * HD + tid + 32] = f2tf(o1);
            } else {
                dstV[((size_t)bh * HD + tid) * NQP]      = f2tf(o0);
                dstV[((size_t)bh * HD + tid + 32) * NQP] = f2tf(o1);
            }
        }
        return;
    }

    const float* wr_ = wsh + d * 27;
    float acc = 0.f;
#pragma unroll
    for (int j = 0; j < 9; j++) {
        const float* row = tile + (j * TX + 2 * xp) * 64 + d;
        acc += row[0]   * wr_[j * 3];
        acc += row[64]  * wr_[j * 3 + 1];
        acc += row[128] * wr_[j * 3 + 2];
    }

    float sum = acc, sq = acc * acc;
#pragma unroll
    for (int off = 16; off > 0; off >>= 1) {
        sum += __shfl_xor_sync(0xffffffffu, sum, off);
        sq  += __shfl_xor_sync(0xffffffffu, sq, off);
    }
    if ((d & 31) == 0) {
        red[xp * 4 + (d >> 5) * 2]     = sum;
        red[xp * 4 + (d >> 5) * 2 + 1] = sq;
    }
    __syncthreads();
    sum = red[xp * 4] + red[xp * 4 + 2];
    sq  = red[xp * 4 + 1] + red[xp * 4 + 3];
    float mean = sum * (1.f / 64.f);
    float var  = sq * (1.f / 64.f) - mean * mean;
    float rstd = rsqrtf(var + 1e-5f);
    float outv = (acc - mean) * rstd * gsh[d] + bsh[d];
    unsigned outu = f2tf(outv);

    int tok = 1 + (tp * 14 + yp) * 14 + xp;
    if (slab == 0) {
        dstQ[((size_t)bh * NQ + tok) * HD + d] = outu;
    } else if (slab == 1) {
        dstK[((size_t)bh * NQ + tok) * HD + d] = outu;
    } else {
        vst[d * 15 + xp] = outu;
        __syncthreads();
        int row = tid / 14;
        int col = tid - row * 14;
        int tokBase = 1 + (tp * 14 + yp) * 14;
        dstV[((size_t)bh * HD + row) * NQP + tokBase + col] = vst[row * 15 + col];
    }
}

// ---------------- flash attention v7: 256 threads, 128 queries/block, 2 CTAs/SM ------------
// smem: Qs 128*AW | Ks 64*AW | Ps 128*AW | Vs 64*AW = 104448 B.
// K/V fill + barriers amortized over 2x queries; K/V L2 streams halved (624 blocks).
__global__ void __launch_bounds__(256, 2) attn_mma(
    const unsigned* __restrict__ Qtg, const unsigned* __restrict__ Ktg,
    const unsigned* __restrict__ Vtg, float* __restrict__ O)
{
    extern __shared__ unsigned smem[];
    unsigned* Qs = smem;                 // 128*AW
    unsigned* Ks = Qs + 128 * AW;        // 64*AW
    unsigned* Ps = Ks + 64 * AW;         // 128*AW
    unsigned* Vs = Ps + 128 * AW;        // 64*AW
    const unsigned sQs = (unsigned)__cvta_generic_to_shared(Qs);
    const unsigned sKs = (unsigned)__cvta_generic_to_shared(Ks);
    const unsigned sPs = (unsigned)__cvta_generic_to_shared(Ps);
    const unsigned sVs = (unsigned)__cvta_generic_to_shared(Vs);

    const int tid  = threadIdx.x;
    const int warp = tid >> 5, lane = tid & 31;
    const int gid  = lane >> 2, tg = lane & 3;
    const int qt   = blockIdx.x, bh = blockIdx.y;
    const int b    = bh / HEADS, h = bh - b * HEADS;
    const unsigned* Qg = Qtg + (size_t)bh * NQ * HD;
    const unsigned* Kg = Ktg + (size_t)bh * NQ * HD;
    const unsigned* Vg = Vtg + (size_t)bh * HD * NQP;   // [d][NQP]
    const int m0 = warp << 4;            // 0..112

    const int aoffw = (lane & 15) * AW + ((lane >> 4) << 2);
    const int boffw = ((lane & 7) + ((lane >> 4) << 3)) * AW + (((lane >> 3) & 1) << 2);

    auto fillK = [&](int kb) {
#pragma unroll
        for (int it = 0; it < 4; it++) {
            int p  = tid + it * 256;
            int r  = p >> 4;
            int c4 = (p & 15) << 2;
            int kg = kb + r;
            cpasync16(sKs + (r * AW + c4) * 4, Kg + (size_t)kg * HD + c4, kg < NQ);
        }
        asm volatile("cp.async.commit_group;");
    };
    auto fillV = [&](int kb) {
#pragma unroll
        for (int it = 0; it < 4; it++) {
            int p  = tid + it * 256;
            int r  = p >> 4;              // d row 0..63
            int c4 = (p & 15) << 2;       // key offset (16B-aligned: NQP%4==0)
            cpasync16(sVs + (r * AW + c4) * 4, Vg + (size_t)r * NQP + kb + c4, true);
        }
        asm volatile("cp.async.commit_group;");
    };

    // prologue: async-load K0, V0, Q (128 rows)
    fillK(0);
    fillV(0);
#pragma unroll
    for (int it = 0; it < 8; it++) {
        int p  = tid + it * 256;
        int r  = p >> 4;
        int c4 = (p & 15) << 2;
        int qg = qt * 128 + r;
        cpasync16(sQs + (r * AW + c4) * 4, Qg + (size_t)qg * HD + c4, qg < NQ);
    }
    asm volatile("cp.async.commit_group;");
    asm volatile("cp.async.wait_group 0;");
    __syncthreads();

    float m0v = -1e30f, m1v = -1e30f, l0 = 0.f, l1 = 0.f;
    float o[8][4];
#pragma unroll
    for (int nb = 0; nb < 8; nb++)
#pragma unroll
        for (int r = 0; r < 4; r++) o[nb][r] = 0.f;

    const int NKT = (NQ + 63) / 64;   // 25
    for (int kt = 0; kt < NKT; kt++) {
        const int kb = kt * 64;
        const bool hasNext = (kt + 1 < NKT);

        // ---- phase A: S = Q K^T (tf32, ldmatrix fragments) ----
        float s[8][4];
#pragma unroll
        for (int nb = 0; nb < 8; nb++)
#pragma unroll
            for (int r = 0; r < 4; r++) s[nb][r] = 0.f;

#pragma unroll
        for (int k8 = 0; k8 < 8; k8++) {
            const int kc = k8 << 3;
            unsigned ah[4], bf[8][2];
            ldmx4(ah[0], ah[1], ah[2], ah[3], sQs + (m0 * AW + kc + aoffw) * 4);
#pragma unroll
            for (int p = 0; p < 4; p++) {
                unsigned bd = sKs + ((p << 4) * AW + kc + boffw) * 4;
                ldmx4(bf[2 * p][0], bf[2 * p][1], bf[2 * p + 1][0], bf[2 * p + 1][1], bd);
            }
#pragma unroll
            for (int nb = 0; nb < 8; nb++)
                mma_tf32(s[nb], ah, bf[nb]);
        }

        // ---- softmax (warp-local) ----
        float mn0 = -1e30f, mn1 = -1e30f;
#pragma unroll
        for (int nb = 0; nb < 8; nb++) {
            int col = kb + (nb << 3) + (tg << 1);
            bool v0 = col < NQ, v1 = (col + 1) < NQ;
            s[nb][0] = v0 ? s[nb][0] * ATT_SCALE : -1e30f;
            s[nb][1] = v1 ? s[nb][1] * ATT_SCALE : -1e30f;
            s[nb][2] = v0 ? s[nb][2] * ATT_SCALE : -1e30f;
            s[nb][3] = v1 ? s[nb][3] * ATT_SCALE : -1e30f;
            mn0 = fmaxf(mn0, fmaxf(s[nb][0], s[nb][1]));
            mn1 = fmaxf(mn1, fmaxf(s[nb][2], s[nb][3]));
        }
        mn0 = fmaxf(mn0, __shfl_xor_sync(0xffffffffu, mn0, 1));
        mn0 = fmaxf(mn0, __shfl_xor_sync(0xffffffffu, mn0, 2));
        mn1 = fmaxf(mn1, __shfl_xor_sync(0xffffffffu, mn1, 1));
        mn1 = fmaxf(mn1, __shfl_xor_sync(0xffffffffu, mn1, 2));
        float M0 = fmaxf(m0v, mn0), M1 = fmaxf(m1v, mn1);
        float a0 = __expf(m0v - M0), a1 = __expf(m1v - M1);

        float ps0 = 0.f, ps1 = 0.f;
#pragma unroll
        for (int nb = 0; nb < 8; nb++) {
            float p0 = __expf(s[nb][0] - M0);
            float p1 = __expf(s[nb][1] - M0);
            float p2 = __expf(s[nb][2] - M1);
            float p3 = __expf(s[nb][3] - M1);
            ps0 += p0 + p1;
            ps1 += p2 + p3;
            int base0 = (m0 + gid) * AW + (nb << 3) + (tg << 1);
            Ps[base0]              = f2tf(p0);
            Ps[base0 + 1]          = f2tf(p1);
            Ps[base0 + 8 * AW]     = f2tf(p2);
            Ps[base0 + 8 * AW + 1] = f2tf(p3);
        }
        ps0 += __shfl_xor_sync(0xffffffffu, ps0, 1);
        ps0 += __shfl_xor_sync(0xffffffffu, ps0, 2);
        ps1 += __shfl_xor_sync(0xffffffffu, ps1, 1);
        ps1 += __shfl_xor_sync(0xffffffffu, ps1, 2);
        l0 = l0 * a0 + ps0;
        l1 = l1 * a1 + ps1;
        m0v = M0; m1v = M1;
#pragma unroll
        for (int nb = 0; nb < 8; nb++) {
            o[nb][0] *= a0; o[nb][1] *= a0;
            o[nb][2] *= a1; o[nb][3] *= a1;
        }

        // ---- K consumed; prefetch next K (overlaps PV). V ready before PV. ----
        __syncthreads();
        if (hasNext) {
            fillK(kb + 64);
            asm volatile("cp.async.wait_group 1;");   // waits prior V (FIFO), K flies
        } else {
            asm volatile("cp.async.wait_group 0;");
        }
        __syncthreads();

        // ---- phase C: O += P V (ldmatrix on Ps and transposed Vs) ----
#pragma unroll
        for (int k8 = 0; k8 < 8; k8++) {
            const int kc = k8 << 3;
            unsigned ap[4], bv[8][2];
            ldmx4(ap[0], ap[1], ap[2], ap[3], sPs + (m0 * AW + kc + aoffw) * 4);
#pragma unroll
            for (int p = 0; p < 4; p++) {
                unsigned bd = sVs + ((p << 4) * AW + kc + boffw) * 4;
                ldmx4(bv[2 * p][0], bv[2 * p][1], bv[2 * p + 1][0], bv[2 * p + 1][1], bd);
            }
#pragma unroll
            for (int nb = 0; nb < 8; nb++)
                mma_tf32(o[nb], ap, bv[nb]);
        }

        // ---- V consumed; prefetch next V; next K ready before next phase A ----
        __syncthreads();
        if (hasNext) {
            fillV(kb + 64);
            asm volatile("cp.async.wait_group 1;");   // waits K (FIFO), V flies
            __syncthreads();
        }
    }

    // epilogue: normalize, write tf32-rounded O (A-operand of proj GEMM)
    int r0 = qt * 128 + m0 + gid;
    float inv0 = 1.f / l0, inv1 = 1.f / l1;
#pragma unroll
    for (int nb = 0; nb < 8; nb++) {
        int col = h * HD + (nb << 3) + (tg << 1);
        if (r0 < NQ) {
            float* dst = O + ((size_t)b * NQ + r0) * DIM + col;
            dst[0] = __uint_as_float(f2tf(o[nb][0] * inv0));
            dst[1] = __uint_as_float(f2tf(o[nb][1] * inv0));
        }
        if (r0 + 8 < NQ) {
            float* dst = O + ((size_t)b * NQ + r0 + 8) * DIM + col;
            dst[0] = __uint_as_float(f2tf(o[nb][2] * inv1));
            dst[1] = __uint_as_float(f2tf(o[nb][3] * inv1));
        }
    }
}

// ---------------- launch ----------------
extern "C" void kernel_launch(void* const* d_in, const int* in_sizes, int n_in,
                              void* d_out, int out_size)
{
    (void)in_sizes; (void)n_in; (void)out_size;
    const float* x      = (const float*)d_in[0];
    const float* qkv_w  = (const float*)d_in[1];
    const float* qkv_b  = (const float*)d_in[2];
    const float* proj_w = (const float*)d_in[3];
    const float* proj_b = (const float*)d_in[4];
    const float* wq     = (const float*)d_in[5];
    const float* wk     = (const float*)d_in[6];
    const float* wv     = (const float*)d_in[7];
    const float* gq     = (const float*)d_in[8];
    const float* bq     = (const float*)d_in[9];
    const float* gk     = (const float*)d_in[10];
    const float* bk     = (const float*)d_in[11];
    const float* gv     = (const float*)d_in[12];
    const float* bv     = (const float*)d_in[13];
    float* out = (float*)d_out;

    float *qkv_s, *att_s;
    unsigned *xt, *wt1, *wt2, *qtb, *ktb, *vtb;
    cudaGetSymbolAddress((void**)&qkv_s, g_qkv);
    cudaGetSymbolAddress((void**)&att_s, g_att);
    cudaGetSymbolAddress((void**)&xt,  g_xt);
    cudaGetSymbolAddress((void**)&wt1, g_wt1);
    cudaGetSymbolAddress((void**)&wt2, g_wt2);
    cudaGetSymbolAddress((void**)&qtb, g_qt);
    cudaGetSymbolAddress((void**)&ktb, g_kt);
    cudaGetSymbolAddress((void**)&vtb, g_vt);

    const int ATTN_SMEM = (128 + 64 + 128 + 64) * AW * 4;          // 104448 B -> 2 CTAs/SM
    const int POOL_SMEM = (9 * TX * 64 + 1728 + 128 + 56 + 960) * 4;
    const int GEMM_SMEM = 3 * GSTG2 * 4;                           // 110592 B
    cudaFuncSetAttribute(attn_mma, cudaFuncAttributeMaxDynamicSharedMemorySize, ATTN_SMEM);
    cudaFuncSetAttribute(pool_ln6, cudaFuncAttributeMaxDynamicSharedMemorySize, POOL_SMEM);
    cudaFuncSetAttribute(gemm_tf32_ldm, cudaFuncAttributeMaxDynamicSharedMemorySize, GEMM_SMEM);

    // 0) operand prep
    {
        int n4x = GM1 * DIM / 4;
        cvt_tf32<<<(n4x + 255) / 256, 256>>>((const float4*)x, (uint4*)xt, n4x);
        transpose_tf32<<<dim3(GN1 / 32, DIM / 32), dim3(32, 8)>>>(qkv_w, wt1, DIM, GN1);
        transpose_tf32<<<dim3(DIM / 32, DIM / 32), dim3(32, 8)>>>(proj_w, wt2, DIM, DIM);
    }

    // 1) QKV GEMM
    gemm_tf32_ldm<<<dim3(GN1 / 128, (GM1 + 127) / 128), 256, GEMM_SMEM>>>(
        xt, wt1, qkv_b, qkv_s, GM1, GN1, DIM);

    // 2) pool + LN
    pool_ln6<<<dim3(113, BB * HEADS, 3), dim3(64, 14), POOL_SMEM>>>(
        qkv_s, wq, wk, wv, gq, bq, gk, bk, gv, bv, qtb, ktb, vtb);

    // 3) flash attention v7 (128 queries/block, 2 CTAs/SM)
    attn_mma<<<dim3((NQ + 127) / 128, BB * HEADS), 256, ATTN_SMEM>>>(
        qtb, ktb, vtb, att_s);

    // 4) output projection
    gemm_tf32_ldm<<<dim3(DIM / 128, (GM2 + 127) / 128), 256, GEMM_SMEM>>>(
        (const unsigned*)att_s, wt2, proj_b, out, GM2, DIM, DIM);
}

// round 17
// speedup vs baseline: 1.0301x; 1.0301x over previous
#include <cuda_runtime.h>
#include <stdint.h>

#define HEADS 12
#define HD    64
#define DIM   768
#define BB    4
#define NTOK  6273          // 1 + 8*28*28
#define NQ    1569          // 1 + 8*14*14
#define NQP   1600          // padded V row pitch (16B-aligned cp.async rows)
#define GM1   25092         // BB*NTOK
#define GN1   2304          // 3*DIM
#define GM2   6276          // BB*NQ
#define QSCALE 0.180336880f // ATT_SCALE * log2(e) = 0.125 * 1.4426950408889634
#define AW    68            // pitch (words) all attention tiles
#define TX    30            // pool tile x extent
#define PSZ   ((size_t)BB * HEADS * NQ * HD)

// ---------------- scratch (static device globals; no allocation) ----------------
__device__ float    g_qkv[(size_t)GM1 * GN1];                    // 231 MB
__device__ unsigned g_qt [PSZ];                                  // Q tf32 (pre-scaled) [bh][tok][d]
__device__ unsigned g_kt [PSZ];                                  // K tf32  [bh][tok][d]
__device__ unsigned g_vt [(size_t)BB * HEADS * HD * NQP];        // V tf32  [bh][d][NQP]
__device__ float    g_att[(size_t)GM2 * DIM];                    // attention out (tf32 bits)
__device__ unsigned g_xt[(size_t)GM1 * DIM];                     // x -> tf32
__device__ unsigned g_wt1[(size_t)GN1 * DIM];                    // qkv_w^T tf32 [N,K]
__device__ unsigned g_wt2[(size_t)DIM * DIM];                    // proj_w^T tf32 [N,K]

// ---------------- TF32 helpers ----------------
__device__ __forceinline__ unsigned f2tf(float x) {
    unsigned u;
    asm("cvt.rna.tf32.f32 %0, %1;" : "=r"(u) : "f"(x));
    return u;
}
__device__ __forceinline__ void mma_tf32(float* c, const unsigned* a, const unsigned* b) {
    asm volatile(
        "mma.sync.aligned.m16n8k8.row.col.f32.tf32.tf32.f32 "
        "{%0,%1,%2,%3}, {%4,%5,%6,%7}, {%8,%9}, {%0,%1,%2,%3};"
        : "+f"(c[0]), "+f"(c[1]), "+f"(c[2]), "+f"(c[3])
        : "r"(a[0]), "r"(a[1]), "r"(a[2]), "r"(a[3]), "r"(b[0]), "r"(b[1]));
}
__device__ __forceinline__ void cpasync16(unsigned smaddr, const void* g, bool pred) {
    int sz = pred ? 16 : 0;
    asm volatile("cp.async.cg.shared.global [%0], [%1], 16, %2;"
                 :: "r"(smaddr), "l"(g), "r"(sz));
}
__device__ __forceinline__ void ldmx4(unsigned& r0, unsigned& r1, unsigned& r2, unsigned& r3,
                                      unsigned smaddr) {
    asm volatile("ldmatrix.sync.aligned.m8n8.x4.shared.b16 {%0,%1,%2,%3}, [%4];"
                 : "=r"(r0), "=r"(r1), "=r"(r2), "=r"(r3) : "r"(smaddr));
}

// ---------------- elementwise x -> tf32 ----------------
__global__ void cvt_tf32(const float4* __restrict__ in, uint4* __restrict__ out, int n4) {
    int i = blockIdx.x * blockDim.x + threadIdx.x;
    if (i < n4) {
        float4 v = in[i];
        out[i] = make_uint4(f2tf(v.x), f2tf(v.y), f2tf(v.z), f2tf(v.w));
    }
}

// ---------------- weight transpose + tf32 round: in[K,N] -> out[N,K] ----------------
__global__ void transpose_tf32(const float* __restrict__ in, unsigned* __restrict__ out,
                               int K, int N)
{
    __shared__ unsigned t[32][33];
    int n0 = blockIdx.x << 5, k0 = blockIdx.y << 5;
    int tx = threadIdx.x, ty = threadIdx.y;   // (32, 8)
#pragma unroll
    for (int j = ty; j < 32; j += 8)
        t[j][tx] = f2tf(in[(size_t)(k0 + j) * N + n0 + tx]);
    __syncthreads();
#pragma unroll
    for (int j = ty; j < 32; j += 8)
        out[(size_t)(n0 + j) * K + k0 + tx] = t[tx][j];
}

// ---------------- GEMM v5 (R15, at legacy-path HW cap): ldmatrix + 3-stage cp.async ---------
#define GSTG2 (2 * 128 * 36)   // words per stage = 9216
__global__ void __launch_bounds__(256, 2) gemm_tf32_ldm(
    const unsigned* __restrict__ A, const unsigned* __restrict__ Bt,
    const float* __restrict__ bias, float* __restrict__ C,
    int M, int N, int K)
{
    extern __shared__ unsigned sm[];
    const unsigned sbase = (unsigned)__cvta_generic_to_shared(sm);

    const int tid  = threadIdx.x;
    const int bn   = blockIdx.x << 7;
    const int bm   = blockIdx.y << 7;
    const int lane = tid & 31, warp = tid >> 5;
    const int wr   = warp >> 2, wc = warp & 3;
    const int gid  = lane >> 2, tg = lane & 3;

    const int aoff = ((lane & 7) + (((lane >> 3) & 1) << 3)) * 36 + ((lane >> 4) << 2);
    const int boff = ((lane & 7) + ((lane >> 4) << 3)) * 36 + (((lane >> 3) & 1) << 2);

    const int ar  = tid >> 3;
    const int ac4 = (tid & 7) << 2;

    float acc[4][4][4];
#pragma unroll
    for (int i = 0; i < 4; i++)
#pragma unroll
        for (int jn = 0; jn < 4; jn++)
#pragma unroll
            for (int r = 0; r < 4; r++) acc[i][jn][r] = 0.f;

    auto loadStage = [&](int i, int s) {
        const int k0 = i << 5;
        const unsigned so = sbase + s * (GSTG2 * 4);
#pragma unroll
        for (int it = 0; it < 4; it++) {
            int r  = ar + it * 32;
            int gr = bm + r;
            cpasync16(so + (r * 36 + ac4) * 4, A + (size_t)gr * K + k0 + ac4, gr < M);
            cpasync16(so + ((128 + r) * 36 + ac4) * 4,
                      Bt + (size_t)(bn + r) * K + k0 + ac4, true);
        }
        asm volatile("cp.async.commit_group;");
    };

    const int nIter = K >> 5;   // 24
    loadStage(0, 0);
    loadStage(1, 1);

    int sIdx = 0;
    for (int i = 0; i < nIter; i++) {
        if (i + 1 < nIter) {
            asm volatile("cp.async.wait_group 1;");
        } else {
            asm volatile("cp.async.wait_group 0;");
        }
        __syncthreads();
        if (i + 2 < nIter) {
            int s2 = sIdx + 2; if (s2 >= 3) s2 -= 3;
            loadStage(i + 2, s2);
        }

        const unsigned Abase = sbase + sIdx * (GSTG2 * 4);
        const unsigned Bbase = Abase + 128 * 36 * 4;
#pragma unroll
        for (int k8 = 0; k8 < 4; k8++) {
            const int kc = k8 << 3;
            unsigned a[4][4], bf[4][2];
#pragma unroll
            for (int ii = 0; ii < 4; ii++) {
                unsigned ad = Abase + (((wr << 6) + (ii << 4)) * 36 + kc + aoff) * 4;
                ldmx4(a[ii][0], a[ii][1], a[ii][2], a[ii][3], ad);
            }
#pragma unroll
            for (int p = 0; p < 2; p++) {
                unsigned bd = Bbase + (((wc << 5) + (p << 4)) * 36 + kc + boff) * 4;
                ldmx4(bf[2 * p][0], bf[2 * p][1], bf[2 * p + 1][0], bf[2 * p + 1][1], bd);
            }
#pragma unroll
            for (int ii = 0; ii < 4; ii++)
#pragma unroll
                for (int jn = 0; jn < 4; jn++)
                    mma_tf32(acc[ii][jn], a[ii], bf[jn]);
        }
        if (++sIdx == 3) sIdx = 0;
    }

#pragma unroll
    for (int i = 0; i < 4; i++) {
        int gr0 = bm + (wr << 6) + (i << 4) + gid;
#pragma unroll
        for (int jn = 0; jn < 4; jn++) {
            int gc = bn + (wc << 5) + (jn << 3) + (tg << 1);
            float b0 = bias[gc], b1 = bias[gc + 1];
            if (gr0 < M) {
                C[(size_t)gr0 * N + gc]     = acc[i][jn][0] + b0;
                C[(size_t)gr0 * N + gc + 1] = acc[i][jn][1] + b1;
            }
            if (gr0 + 8 < M) {
                C[(size_t)(gr0 + 8) * N + gc]     = acc[i][jn][2] + b0;
                C[(size_t)(gr0 + 8) * N + gc + 1] = acc[i][jn][3] + b1;
            }
        }
    }
}

// ---------------- pool + LN v7: Q pre-scaled by QSCALE; coalesced transposed V ----------
__global__ void __launch_bounds__(896) pool_ln7(
    const float* __restrict__ qkv,
    const float* __restrict__ wq, const float* __restrict__ wk, const float* __restrict__ wv,
    const float* __restrict__ gq, const float* __restrict__ bq,
    const float* __restrict__ gk, const float* __restrict__ bk,
    const float* __restrict__ gv, const float* __restrict__ bv,
    unsigned* __restrict__ dstQ, unsigned* __restrict__ dstK, unsigned* __restrict__ dstV)
{
    extern __shared__ float sp[];
    float*    tile = sp;
    float*    wsh  = tile + 9 * TX * 64;
    float*    gsh  = wsh + 1728;
    float*    bsh  = gsh + 64;
    float*    red  = bsh + 64;
    unsigned* vst  = (unsigned*)(red + 56);

    const int slab = blockIdx.z;
    const float* wconv = slab == 0 ? wq : slab == 1 ? wk : wv;
    const float* gamma = slab == 0 ? gq : slab == 1 ? gk : gv;
    const float* beta  = slab == 0 ? bq : slab == 1 ? bk : bv;

    const int bh = blockIdx.y;
    const int b  = bh / HEADS, h = bh - b * HEADS;
    const int d  = threadIdx.x;
    const int xp = threadIdx.y;
    const int tid = d + (xp << 6);
    const bool is_cls = (blockIdx.x == 112);

    for (int i = tid; i < 1728; i += 896) wsh[i] = wconv[i];
    if (tid < 64) { gsh[tid] = gamma[tid]; bsh[tid] = beta[tid]; }

    const float* base = qkv + (size_t)b * NTOK * GN1 + slab * DIM + h * HD;

    int tp = 0, yp = 0;
    if (!is_cls) {
        tp = blockIdx.x / 14;
        yp = blockIdx.x - tp * 14;
        for (int i = tid; i < 9 * 2 * 64; i += 896) {
            int rr = i >> 7;
            int cc = (i >> 6) & 1;
            int dd = i & 63;
            tile[(rr * TX + cc * 29) * 64 + dd] = 0.f;
        }
        for (int i = tid; i < 252 * 16; i += 896) {
            int s  = i >> 4, f4 = i & 15;
            int kt = s / 84;  int r = s - kt * 84;
            int ky = r / 28;  int x = r - ky * 28;
            int t  = tp + kt - 1;
            int y  = 2 * yp + ky - 1;
            float4 v = make_float4(0.f, 0.f, 0.f, 0.f);
            if ((unsigned)t < 8u && (unsigned)y < 28u) {
                int n = 1 + (t * 28 + y) * 28 + x;
                v = *(const float4*)(base + (size_t)n * GN1 + (f4 << 2));
            }
            float* tdst = tile + ((kt * 3 + ky) * TX + x + 1) * 64 + (f4 << 2);
            tdst[0] = v.x; tdst[1] = v.y; tdst[2] = v.z; tdst[3] = v.w;
        }
    }
    __syncthreads();

    if (is_cls) {
        if (tid < 32) {
            float v0 = base[tid];
            float v1 = base[tid + 32];
            float sum = v0 + v1, sq = v0 * v0 + v1 * v1;
#pragma unroll
            for (int off = 16; off > 0; off >>= 1) {
                sum += __shfl_xor_sync(0xffffffffu, sum, off);
                sq  += __shfl_xor_sync(0xffffffffu, sq, off);
            }
            float mean = sum * (1.f / 64.f);
            float var  = sq * (1.f / 64.f) - mean * mean;
            float rstd = rsqrtf(var + 1e-5f);
            float o0 = (v0 - mean) * rstd * gsh[tid]      + bsh[tid];
            float o1 = (v1 - mean) * rstd * gsh[tid + 32] + bsh[tid + 32];
            if (slab == 0) {
                dstQ[(size_t)bh * NQ * HD + tid]      = f2tf(o0 * QSCALE);
                dstQ[(size_t)bh * NQ * HD + tid + 32] = f2tf(o1 * QSCALE);
            } else if (slab == 1) {
                dstK[(size_t)bh * NQ * HD + tid]      = f2tf(o0);
                dstK[(size_t)bh * NQ * HD + tid + 32] = f2tf(o1);
            } else {
                dstV[((size_t)bh * HD + tid) * NQP]      = f2tf(o0);
                dstV[((size_t)bh * HD + tid + 32) * NQP] = f2tf(o1);
            }
        }
        return;
    }

    const float* wr_ = wsh + d * 27;
    float acc = 0.f;
#pragma unroll
    for (int j = 0; j < 9; j++) {
        const float* row = tile + (j * TX + 2 * xp) * 64 + d;
        acc += row[0]   * wr_[j * 3];
        acc += row[64]  * wr_[j * 3 + 1];
        acc += row[128] * wr_[j * 3 + 2];
    }

    float sum = acc, sq = acc * acc;
#pragma unroll
    for (int off = 16; off > 0; off >>= 1) {
        sum += __shfl_xor_sync(0xffffffffu, sum, off);
        sq  += __shfl_xor_sync(0xffffffffu, sq, off);
    }
    if ((d & 31) == 0) {
        red[xp * 4 + (d >> 5) * 2]     = sum;
        red[xp * 4 + (d >> 5) * 2 + 1] = sq;
    }
    __syncthreads();
    sum = red[xp * 4] + red[xp * 4 + 2];
    sq  = red[xp * 4 + 1] + red[xp * 4 + 3];
    float mean = sum * (1.f / 64.f);
    float var  = sq * (1.f / 64.f) - mean * mean;
    float rstd = rsqrtf(var + 1e-5f);
    float outv = (acc - mean) * rstd * gsh[d] + bsh[d];

    int tok = 1 + (tp * 14 + yp) * 14 + xp;
    if (slab == 0) {
        dstQ[((size_t)bh * NQ + tok) * HD + d] = f2tf(outv * QSCALE);
    } else if (slab == 1) {
        dstK[((size_t)bh * NQ + tok) * HD + d] = f2tf(outv);
    } else {
        vst[d * 15 + xp] = f2tf(outv);
        __syncthreads();
        int row = tid / 14;
        int col = tid - row * 14;
        int tokBase = 1 + (tp * 14 + yp) * 14;
        dstV[((size_t)bh * HD + row) * NQP + tokBase + col] = vst[row * 15 + col];
    }
}

// ---------------- flash attention v8 (R15 shape): full-ldmatrix, exp2 softmax ---------------
// smem: Qs, Ks, Ps, Vs each 64*AW words = 69632 B -> 3 CTAs/SM. Scores in log2 domain.
__global__ void __launch_bounds__(128) attn_mma(
    const unsigned* __restrict__ Qtg, const unsigned* __restrict__ Ktg,
    const unsigned* __restrict__ Vtg, float* __restrict__ O)
{
    extern __shared__ unsigned smem[];
    unsigned* Qs = smem;
    unsigned* Ks = Qs + 64 * AW;
    unsigned* Ps = Ks + 64 * AW;
    unsigned* Vs = Ps + 64 * AW;
    const unsigned sQs = (unsigned)__cvta_generic_to_shared(Qs);
    const unsigned sKs = (unsigned)__cvta_generic_to_shared(Ks);
    const unsigned sPs = (unsigned)__cvta_generic_to_shared(Ps);
    const unsigned sVs = (unsigned)__cvta_generic_to_shared(Vs);

    const int tid  = threadIdx.x;
    const int warp = tid >> 5, lane = tid & 31;
    const int gid  = lane >> 2, tg = lane & 3;
    const int qt   = blockIdx.x, bh = blockIdx.y;
    const int b    = bh / HEADS, h = bh - b * HEADS;
    const unsigned* Qg = Qtg + (size_t)bh * NQ * HD;
    const unsigned* Kg = Ktg + (size_t)bh * NQ * HD;
    const unsigned* Vg = Vtg + (size_t)bh * HD * NQP;   // [d][NQP]
    const int m0 = warp << 4;

    const int aoffw = (lane & 15) * AW + ((lane >> 4) << 2);
    const int boffw = ((lane & 7) + ((lane >> 4) << 3)) * AW + (((lane >> 3) & 1) << 2);

    auto fillK = [&](int kb) {
#pragma unroll
        for (int it = 0; it < 8; it++) {
            int p  = tid + it * 128;
            int r  = p >> 4;
            int c4 = (p & 15) << 2;
            int kg = kb + r;
            cpasync16(sKs + (r * AW + c4) * 4, Kg + (size_t)kg * HD + c4, kg < NQ);
        }
        asm volatile("cp.async.commit_group;");
    };
    auto fillV = [&](int kb) {
#pragma unroll
        for (int it = 0; it < 8; it++) {
            int p  = tid + it * 128;
            int r  = p >> 4;              // d row 0..63
            int c4 = (p & 15) << 2;       // key offset (16B-aligned: NQP%4==0)
            cpasync16(sVs + (r * AW + c4) * 4, Vg + (size_t)r * NQP + kb + c4, true);
        }
        asm volatile("cp.async.commit_group;");
    };

    fillK(0);
    fillV(0);
#pragma unroll
    for (int it = 0; it < 8; it++) {
        int p  = tid + it * 128;
        int r  = p >> 4;
        int c4 = (p & 15) << 2;
        int qg = qt * 64 + r;
        cpasync16(sQs + (r * AW + c4) * 4, Qg + (size_t)qg * HD + c4, qg < NQ);
    }
    asm volatile("cp.async.commit_group;");
    asm volatile("cp.async.wait_group 0;");
    __syncthreads();

    float m0v = -1e30f, m1v = -1e30f, l0 = 0.f, l1 = 0.f;
    float o[8][4];
#pragma unroll
    for (int nb = 0; nb < 8; nb++)
#pragma unroll
        for (int r = 0; r < 4; r++) o[nb][r] = 0.f;

    const int NKT = (NQ + 63) / 64;   // 25
    for (int kt = 0; kt < NKT; kt++) {
        const int kb = kt * 64;
        const bool hasNext = (kt + 1 < NKT);

        // ---- phase A: S = Q K^T (log2-domain scores; Q pre-scaled) ----
        float s[8][4];
#pragma unroll
        for (int nb = 0; nb < 8; nb++)
#pragma unroll
            for (int r = 0; r < 4; r++) s[nb][r] = 0.f;

#pragma unroll
        for (int k8 = 0; k8 < 8; k8++) {
            const int kc = k8 << 3;
            unsigned ah[4], bf[8][2];
            ldmx4(ah[0], ah[1], ah[2], ah[3], sQs + (m0 * AW + kc + aoffw) * 4);
#pragma unroll
            for (int p = 0; p < 4; p++) {
                unsigned bd = sKs + ((p << 4) * AW + kc + boffw) * 4;
                ldmx4(bf[2 * p][0], bf[2 * p][1], bf[2 * p + 1][0], bf[2 * p + 1][1], bd);
            }
#pragma unroll
            for (int nb = 0; nb < 8; nb++)
                mma_tf32(s[nb], ah, bf[nb]);
        }

        // ---- softmax (warp-local, exp2 domain) ----
        float mn0 = -1e30f, mn1 = -1e30f;
#pragma unroll
        for (int nb = 0; nb < 8; nb++) {
            int col = kb + (nb << 3) + (tg << 1);
            bool v0 = col < NQ, v1 = (col + 1) < NQ;
            s[nb][0] = v0 ? s[nb][0] : -1e30f;
            s[nb][1] = v1 ? s[nb][1] : -1e30f;
            s[nb][2] = v0 ? s[nb][2] : -1e30f;
            s[nb][3] = v1 ? s[nb][3] : -1e30f;
            mn0 = fmaxf(mn0, fmaxf(s[nb][0], s[nb][1]));
            mn1 = fmaxf(mn1, fmaxf(s[nb][2], s[nb][3]));
        }
        mn0 = fmaxf(mn0, __shfl_xor_sync(0xffffffffu, mn0, 1));
        mn0 = fmaxf(mn0, __shfl_xor_sync(0xffffffffu, mn0, 2));
        mn1 = fmaxf(mn1, __shfl_xor_sync(0xffffffffu, mn1, 1));
        mn1 = fmaxf(mn1, __shfl_xor_sync(0xffffffffu, mn1, 2));
        float M0 = fmaxf(m0v, mn0), M1 = fmaxf(m1v, mn1);
        float a0 = exp2f(m0v - M0), a1 = exp2f(m1v - M1);

        float ps0 = 0.f, ps1 = 0.f;
#pragma unroll
        for (int nb = 0; nb < 8; nb++) {
            float p0 = exp2f(s[nb][0] - M0);
            float p1 = exp2f(s[nb][1] - M0);
            float p2 = exp2f(s[nb][2] - M1);
            float p3 = exp2f(s[nb][3] - M1);
            ps0 += p0 + p1;
            ps1 += p2 + p3;
            int base0 = (m0 + gid) * AW + (nb << 3) + (tg << 1);
            Ps[base0]              = f2tf(p0);
            Ps[base0 + 1]          = f2tf(p1);
            Ps[base0 + 8 * AW]     = f2tf(p2);
            Ps[base0 + 8 * AW + 1] = f2tf(p3);
        }
        ps0 += __shfl_xor_sync(0xffffffffu, ps0, 1);
        ps0 += __shfl_xor_sync(0xffffffffu, ps0, 2);
        ps1 += __shfl_xor_sync(0xffffffffu, ps1, 1);
        ps1 += __shfl_xor_sync(0xffffffffu, ps1, 2);
        l0 = l0 * a0 + ps0;
        l1 = l1 * a1 + ps1;
        m0v = M0; m1v = M1;
#pragma unroll
        for (int nb = 0; nb < 8; nb++) {
            o[nb][0] *= a0; o[nb][1] *= a0;
            o[nb][2] *= a1; o[nb][3] *= a1;
        }

        // ---- K consumed; prefetch next K (overlaps PV). V ready before PV. ----
        __syncthreads();
        if (hasNext) {
            fillK(kb + 64);
            asm volatile("cp.async.wait_group 1;");
        } else {
            asm volatile("cp.async.wait_group 0;");
        }
        __syncthreads();

        // ---- phase C: O += P V (ldmatrix on Ps and transposed Vs) ----
#pragma unroll
        for (int k8 = 0; k8 < 8; k8++) {
            const int kc = k8 << 3;
            unsigned ap[4], bv[8][2];
            ldmx4(ap[0], ap[1], ap[2], ap[3], sPs + (m0 * AW + kc + aoffw) * 4);
#pragma unroll
            for (int p = 0; p < 4; p++) {
                unsigned bd = sVs + ((p << 4) * AW + kc + boffw) * 4;
                ldmx4(bv[2 * p][0], bv[2 * p][1], bv[2 * p + 1][0], bv[2 * p + 1][1], bd);
            }
#pragma unroll
            for (int nb = 0; nb < 8; nb++)
                mma_tf32(o[nb], ap, bv[nb]);
        }

        // ---- V consumed; prefetch next V; next K ready before next phase A ----
        __syncthreads();
        if (hasNext) {
            fillV(kb + 64);
            asm volatile("cp.async.wait_group 1;");
            __syncthreads();
        }
    }

    // epilogue: normalize, write tf32-rounded O (A-operand of proj GEMM)
    int r0 = qt * 64 + m0 + gid;
    float inv0 = 1.f / l0, inv1 = 1.f / l1;
#pragma unroll
    for (int nb = 0; nb < 8; nb++) {
        int col = h * HD + (nb << 3) + (tg << 1);
        if (r0 < NQ) {
            float* dst = O + ((size_t)b * NQ + r0) * DIM + col;
            dst[0] = __uint_as_float(f2tf(o[nb][0] * inv0));
            dst[1] = __uint_as_float(f2tf(o[nb][1] * inv0));
        }
        if (r0 + 8 < NQ) {
            float* dst = O + ((size_t)b * NQ + r0 + 8) * DIM + col;
            dst[0] = __uint_as_float(f2tf(o[nb][2] * inv1));
            dst[1] = __uint_as_float(f2tf(o[nb][3] * inv1));
        }
    }
}

// ---------------- launch ----------------
extern "C" void kernel_launch(void* const* d_in, const int* in_sizes, int n_in,
                              void* d_out, int out_size)
{
    (void)in_sizes; (void)n_in; (void)out_size;
    const float* x      = (const float*)d_in[0];
    const float* qkv_w  = (const float*)d_in[1];
    const float* qkv_b  = (const float*)d_in[2];
    const float* proj_w = (const float*)d_in[3];
    const float* proj_b = (const float*)d_in[4];
    const float* wq     = (const float*)d_in[5];
    const float* wk     = (const float*)d_in[6];
    const float* wv     = (const float*)d_in[7];
    const float* gq     = (const float*)d_in[8];
    const float* bq     = (const float*)d_in[9];
    const float* gk     = (const float*)d_in[10];
    const float* bk     = (const float*)d_in[11];
    const float* gv     = (const float*)d_in[12];
    const float* bv     = (const float*)d_in[13];
    float* out = (float*)d_out;

    float *qkv_s, *att_s;
    unsigned *xt, *wt1, *wt2, *qtb, *ktb, *vtb;
    cudaGetSymbolAddress((void**)&qkv_s, g_qkv);
    cudaGetSymbolAddress((void**)&att_s, g_att);
    cudaGetSymbolAddress((void**)&xt,  g_xt);
    cudaGetSymbolAddress((void**)&wt1, g_wt1);
    cudaGetSymbolAddress((void**)&wt2, g_wt2);
    cudaGetSymbolAddress((void**)&qtb, g_qt);
    cudaGetSymbolAddress((void**)&ktb, g_kt);
    cudaGetSymbolAddress((void**)&vtb, g_vt);

    const int ATTN_SMEM = 4 * 64 * AW * 4;                         // 69632 B -> 3 CTAs/SM
    const int POOL_SMEM = (9 * TX * 64 + 1728 + 128 + 56 + 960) * 4;
    const int GEMM_SMEM = 3 * GSTG2 * 4;                           // 110592 B
    cudaFuncSetAttribute(attn_mma, cudaFuncAttributeMaxDynamicSharedMemorySize, ATTN_SMEM);
    cudaFuncSetAttribute(pool_ln7, cudaFuncAttributeMaxDynamicSharedMemorySize, POOL_SMEM);
    cudaFuncSetAttribute(gemm_tf32_ldm, cudaFuncAttributeMaxDynamicSharedMemorySize, GEMM_SMEM);

    // 0) operand prep
    {
        int n4x = GM1 * DIM / 4;
        cvt_tf32<<<(n4x + 255) / 256, 256>>>((const float4*)x, (uint4*)xt, n4x);
        transpose_tf32<<<dim3(GN1 / 32, DIM / 32), dim3(32, 8)>>>(qkv_w, wt1, DIM, GN1);
        transpose_tf32<<<dim3(DIM / 32, DIM / 32), dim3(32, 8)>>>(proj_w, wt2, DIM, DIM);
    }

    // 1) QKV GEMM
    gemm_tf32_ldm<<<dim3(GN1 / 128, (GM1 + 127) / 128), 256, GEMM_SMEM>>>(
        xt, wt1, qkv_b, qkv_s, GM1, GN1, DIM);

    // 2) pool + LN (Q pre-scaled for exp2 softmax)
    pool_ln7<<<dim3(113, BB * HEADS, 3), dim3(64, 14), POOL_SMEM>>>(
        qkv_s, wq, wk, wv, gq, bq, gk, bk, gv, bv, qtb, ktb, vtb);

    // 3) flash attention v8 (R15 shape, exp2 softmax)
    attn_mma<<<dim3((NQ + 63) / 64, BB * HEADS), 128, ATTN_SMEM>>>(
        qtb, ktb, vtb, att_s);

    // 4) output projection
    gemm_tf32_ldm<<<dim3(DIM / 128, (GM2 + 127) / 128), 256, GEMM_SMEM>>>(
        (const unsigned*)att_s, wt2, proj_b, out, GM2, DIM, DIM);
}